// round 16
// baseline (speedup 1.0000x reference)
#include <cuda_runtime.h>
#include <cstdint>

#define D 128
#define NMAX 50000
#define EMAX 600000
#define CAP 64
#define NT ((NMAX + 127) / 128)        // 391 row-tiles

// allocation-free scratch
// g_aggp: agg rows as tf32 bits in mma-FRAGMENT order, tiled by 128 rows.
__device__ uint32_t g_aggp[(size_t)NT * 16384];
__device__ int      g_cnt[NMAX];
__device__ int      g_eid[(size_t)NMAX * CAP];   // fixed-capacity buckets
// g_Wtp: W as tf32 bits in fragment order.
__device__ uint32_t g_Wtp[D * D];

__device__ __forceinline__ uint32_t f2tf32(float x) {
    uint32_t r;
    asm("cvt.rna.tf32.f32 %0, %1;" : "=r"(r) : "f"(x));
    return r;
}

// ================= bucket fill + W permute (1 kernel, no barriers) ==========
// cnt is zeroed by a memset node before this kernel.
__global__ void __launch_bounds__(256)
fill_kernel(const int* __restrict__ dst, const float* __restrict__ W, int E) {
    const int gt = blockIdx.x * 256 + threadIdx.x;
    const int stride = gridDim.x * 256;

    // W -> fragment-order tf32 (16K elements; first few blocks only)
    for (int x = gt; x < D * D; x += stride) {
        int j = x >> 7;          // output column (W row)
        int k = x & 127;         // k index
        uint32_t addr = ((uint32_t)(j >> 6)) * 8192u
                      + ((uint32_t)(k >> 3)) * 512u
                      + ((uint32_t)((j >> 4) & 3)) * 128u
                      + ((uint32_t)(((j & 7) << 2) | (k & 3))) * 4u
                      + ((uint32_t)((j >> 3) & 1)) * 2u
                      + ((uint32_t)((k >> 2) & 1));
        g_Wtp[addr] = f2tf32(__ldg(W + x));
    }

    // bucket fill (int4-batched: 4 independent atomics in flight)
    const int E4 = E >> 2;
    const int4* dst4 = (const int4*)dst;
    for (int q = gt; q < E4; q += stride) {
        int4 d4 = __ldg(dst4 + q);
        int e = q * 4;
        int p0 = min(atomicAdd(&g_cnt[d4.x], 1), CAP - 1);
        int p1 = min(atomicAdd(&g_cnt[d4.y], 1), CAP - 1);
        int p2 = min(atomicAdd(&g_cnt[d4.z], 1), CAP - 1);
        int p3 = min(atomicAdd(&g_cnt[d4.w], 1), CAP - 1);
        g_eid[(size_t)d4.x * CAP + p0] = e;
        g_eid[(size_t)d4.y * CAP + p1] = e + 1;
        g_eid[(size_t)d4.z * CAP + p2] = e + 2;
        g_eid[(size_t)d4.w * CAP + p3] = e + 3;
    }
    for (int e = E4 * 4 + gt; e < E; e += stride) {
        int d = __ldg(dst + e);
        int pos = min(atomicAdd(&g_cnt[d], 1), CAP - 1);
        g_eid[(size_t)d * CAP + pos] = e;
    }
}

// ============================ gather ========================================
// 512 threads = 16 warps = 16 nodes (one aligned fragment row-group).
// Each warp: aggRow = h[n] * sum_{e in bucket(n)} e_h[e]  -> smem
// Then one coalesced fragment-order write pass (STG.128, 512B/warp-instr).
#define GLDP 132

__global__ void __launch_bounds__(512)
gather_kernel(const float* __restrict__ h,
              const float* __restrict__ e_h,
              int N) {
    __shared__ float sm[16 * GLDP];

    const int tid  = threadIdx.x;
    const int wid  = tid >> 5;         // 0..15 = local row
    const int lane = tid & 31;
    const int nb   = blockIdx.x * 16;  // node base (16-aligned; N % 16 == 0)
    const int n    = nb + wid;

    float rx = 0.f, ry = 0.f, rz = 0.f, rw = 0.f;
    if (n < N) {
        int s = n * CAP;
        int t = s + min(__ldg(g_cnt + n), CAP);

        float4 a0 = make_float4(0.f, 0.f, 0.f, 0.f);
        float4 a1 = make_float4(0.f, 0.f, 0.f, 0.f);
        float4 a2 = make_float4(0.f, 0.f, 0.f, 0.f);
        float4 a3 = make_float4(0.f, 0.f, 0.f, 0.f);

        int i = s;
        for (; i + 7 < t; i += 8) {
            int e0 = __ldg(g_eid + i);
            int e1 = __ldg(g_eid + i + 1);
            int e2 = __ldg(g_eid + i + 2);
            int e3 = __ldg(g_eid + i + 3);
            int e4 = __ldg(g_eid + i + 4);
            int e5 = __ldg(g_eid + i + 5);
            int e6 = __ldg(g_eid + i + 6);
            int e7 = __ldg(g_eid + i + 7);
            float4 v0 = ((const float4*)(e_h + (size_t)e0 * D))[lane];
            float4 v1 = ((const float4*)(e_h + (size_t)e1 * D))[lane];
            float4 v2 = ((const float4*)(e_h + (size_t)e2 * D))[lane];
            float4 v3 = ((const float4*)(e_h + (size_t)e3 * D))[lane];
            float4 v4 = ((const float4*)(e_h + (size_t)e4 * D))[lane];
            float4 v5 = ((const float4*)(e_h + (size_t)e5 * D))[lane];
            float4 v6 = ((const float4*)(e_h + (size_t)e6 * D))[lane];
            float4 v7 = ((const float4*)(e_h + (size_t)e7 * D))[lane];
            a0.x += v0.x; a0.y += v0.y; a0.z += v0.z; a0.w += v0.w;
            a1.x += v1.x; a1.y += v1.y; a1.z += v1.z; a1.w += v1.w;
            a2.x += v2.x; a2.y += v2.y; a2.z += v2.z; a2.w += v2.w;
            a3.x += v3.x; a3.y += v3.y; a3.z += v3.z; a3.w += v3.w;
            a0.x += v4.x; a0.y += v4.y; a0.z += v4.z; a0.w += v4.w;
            a1.x += v5.x; a1.y += v5.y; a1.z += v5.z; a1.w += v5.w;
            a2.x += v6.x; a2.y += v6.y; a2.z += v6.z; a2.w += v6.w;
            a3.x += v7.x; a3.y += v7.y; a3.z += v7.z; a3.w += v7.w;
        }
        for (; i + 3 < t; i += 4) {
            int e0 = __ldg(g_eid + i);
            int e1 = __ldg(g_eid + i + 1);
            int e2 = __ldg(g_eid + i + 2);
            int e3 = __ldg(g_eid + i + 3);
            float4 v0 = ((const float4*)(e_h + (size_t)e0 * D))[lane];
            float4 v1 = ((const float4*)(e_h + (size_t)e1 * D))[lane];
            float4 v2 = ((const float4*)(e_h + (size_t)e2 * D))[lane];
            float4 v3 = ((const float4*)(e_h + (size_t)e3 * D))[lane];
            a0.x += v0.x; a0.y += v0.y; a0.z += v0.z; a0.w += v0.w;
            a1.x += v1.x; a1.y += v1.y; a1.z += v1.z; a1.w += v1.w;
            a2.x += v2.x; a2.y += v2.y; a2.z += v2.z; a2.w += v2.w;
            a3.x += v3.x; a3.y += v3.y; a3.z += v3.z; a3.w += v3.w;
        }
        for (; i < t; i++) {
            int e0 = __ldg(g_eid + i);
            float4 v0 = ((const float4*)(e_h + (size_t)e0 * D))[lane];
            a0.x += v0.x; a0.y += v0.y; a0.z += v0.z; a0.w += v0.w;
        }

        float4 hv = ((const float4*)(h + (size_t)n * D))[lane];
        rx = (a0.x + a1.x + a2.x + a3.x) * hv.x;
        ry = (a0.y + a1.y + a2.y + a3.y) * hv.y;
        rz = (a0.z + a1.z + a2.z + a3.z) * hv.z;
        rw = (a0.w + a1.w + a2.w + a3.w) * hv.w;
    }

    // stage row in smem: sm[wid][4*lane .. 4*lane+3]
    float4* sp = (float4*)(sm + wid * GLDP + lane * 4);
    *sp = make_float4(rx, ry, rz, rw);
    __syncthreads();

    // coalesced fragment-order write: thread t -> one uint4
    //   ks = t>>5, within = t&31; gid = within>>2, j = within&3
    //   words: [gid][8ks+j], [gid+8][8ks+j], [gid][8ks+j+4], [gid+8][8ks+j+4]
    {
        const int ks     = tid >> 5;
        const int within = tid & 31;
        const int gid    = within >> 2;
        const int j      = within & 3;
        const int kbase  = ks * 8 + j;

        uint4 v;
        v.x = f2tf32(sm[(size_t)gid * GLDP + kbase]);
        v.y = f2tf32(sm[(size_t)(gid + 8) * GLDP + kbase]);
        v.z = f2tf32(sm[(size_t)gid * GLDP + kbase + 4]);
        v.w = f2tf32(sm[(size_t)(gid + 8) * GLDP + kbase + 4]);

        const int tile = nb >> 7;
        const int mg   = (nb >> 5) & 3;
        const int mt   = (nb >> 4) & 1;
        uint32_t* dstp = g_aggp + (size_t)tile * 16384 + mg * 4096
                       + ks * 256 + mt * 128 + within * 4;
        *(uint4*)dstp = v;
    }
}

// ====================== TF32 mma.sync GEMM (fragment-direct) ================
__device__ __forceinline__ void mma_tf32(float* c, const uint32_t* a, const uint32_t* bb) {
    asm volatile(
        "mma.sync.aligned.m16n8k8.row.col.f32.tf32.tf32.f32 "
        "{%0,%1,%2,%3}, {%4,%5,%6,%7}, {%8,%9}, {%0,%1,%2,%3};"
        : "+f"(c[0]), "+f"(c[1]), "+f"(c[2]), "+f"(c[3])
        : "r"(a[0]), "r"(a[1]), "r"(a[2]), "r"(a[3]), "r"(bb[0]), "r"(bb[1]));
}

__global__ void __launch_bounds__(256, 2)
gemm_mma_kernel(const float* __restrict__ b,
                const float* __restrict__ norm,
                float* __restrict__ out,
                int N) {
    const int tid  = threadIdx.x;
    const int wid  = tid >> 5;
    const int lane = tid & 31;
    const int mg   = wid & 3;
    const int ng   = wid >> 2;
    const int rowBase = blockIdx.x * 128;

    const uint32_t* Ab = g_aggp + (size_t)blockIdx.x * 16384 + mg * 4096 + lane * 4;
    const uint32_t* Bb = g_Wtp + ng * 8192 + lane * 4;

    float acc[16][4];
    #pragma unroll
    for (int q = 0; q < 16; q++)
        #pragma unroll
        for (int j = 0; j < 4; j++) acc[q][j] = 0.0f;

    #pragma unroll
    for (int ks = 0; ks < 16; ks++) {
        uint32_t a[2][4];
        #pragma unroll
        for (int mt = 0; mt < 2; mt++) {
            uint4 av = __ldg((const uint4*)(Ab + ks * 256 + mt * 128));
            a[mt][0] = av.x; a[mt][1] = av.y; a[mt][2] = av.z; a[mt][3] = av.w;
        }
        uint32_t bf[8][2];
        #pragma unroll
        for (int nt2 = 0; nt2 < 4; nt2++) {
            uint4 bv = __ldg((const uint4*)(Bb + ks * 512 + nt2 * 128));
            bf[nt2 * 2 + 0][0] = bv.x; bf[nt2 * 2 + 0][1] = bv.y;
            bf[nt2 * 2 + 1][0] = bv.z; bf[nt2 * 2 + 1][1] = bv.w;
        }
        #pragma unroll
        for (int mt = 0; mt < 2; mt++)
            #pragma unroll
            for (int nt = 0; nt < 8; nt++)
                mma_tf32(acc[mt * 8 + nt], a[mt], bf[nt]);
    }

    const int gID = lane >> 2;
    const int tig = lane & 3;
    const int mBase = mg * 32;
    const int nBase = ng * 64;

    #pragma unroll
    for (int mt = 0; mt < 2; mt++) {
        #pragma unroll
        for (int half = 0; half < 2; half++) {
            int m = rowBase + mBase + mt * 16 + half * 8 + gID;
            if (m >= N) continue;
            float nm = __ldg(norm + m);
            #pragma unroll
            for (int nt = 0; nt < 8; nt++) {
                int jcol = nBase + (nt >> 1) * 16 + (nt & 1) * 8;
                float2 bb = *(const float2*)(b + jcol + tig * 2);
                float2 r;
                r.x = (acc[mt * 8 + nt][half * 2 + 0] + bb.x) * nm;
                r.y = (acc[mt * 8 + nt][half * 2 + 1] + bb.y) * nm;
                *(float2*)(out + (size_t)m * D + jcol + tig * 2) = r;
            }
        }
    }
}

// ============================ launch ========================================
extern "C" void kernel_launch(void* const* d_in, const int* in_sizes, int n_in,
                              void* d_out, int out_size) {
    const float* h    = (const float*)d_in[0];
    const float* e_h  = (const float*)d_in[1];
    const float* norm = (const float*)d_in[2];
    const int*   dst  = (const int*)d_in[3];
    const float* W    = (const float*)d_in[4];
    const float* b    = (const float*)d_in[5];
    float*       out  = (float*)d_out;

    const int N = in_sizes[2];
    const int E = in_sizes[3];

    int* cntp = nullptr;
    cudaGetSymbolAddress((void**)&cntp, g_cnt);
    cudaMemsetAsync(cntp, 0, (size_t)N * sizeof(int), 0);

    {   // one int4 per thread
        int blocks = ((E >> 2) + 255) / 256;
        fill_kernel<<<blocks, 256>>>(dst, W, E);
    }
    gather_kernel<<<(N + 15) / 16, 512>>>(h, e_h, N);
    gemm_mma_kernel<<<(N + 127) / 128, 256>>>(b, norm, out, N);
}

// round 17
// speedup vs baseline: 1.2118x; 1.2118x over previous
#include <cuda_runtime.h>
#include <cstdint>

#define D 128
#define NMAX 50000
#define EMAX 600000
#define CAP 64
#define NT ((NMAX + 127) / 128)        // 391 row-tiles
#define GLDP 132

// allocation-free scratch
// g_aggp: agg rows as tf32 bits in mma-FRAGMENT order, tiled by 128 rows.
__device__ uint32_t g_aggp[(size_t)NT * 16384];
__device__ int      g_cnt[NMAX];
__device__ int      g_eid[(size_t)NMAX * CAP];   // fixed-capacity buckets
// g_Wtp: W as tf32 bits in fragment order.
__device__ uint32_t g_Wtp[D * D];

__device__ __forceinline__ uint32_t f2tf32(float x) {
    uint32_t r;
    asm("cvt.rna.tf32.f32 %0, %1;" : "=r"(r) : "f"(x));
    return r;
}

// ================= bucket fill + W permute (1 kernel, no barriers) ==========
// cnt is zeroed by a memset node before this kernel.
__global__ void __launch_bounds__(256)
fill_kernel(const int* __restrict__ dst, const float* __restrict__ W, int E) {
    const int gt = blockIdx.x * 256 + threadIdx.x;
    const int stride = gridDim.x * 256;

    // W -> fragment-order tf32 (16K elements; first few blocks only)
    for (int x = gt; x < D * D; x += stride) {
        int j = x >> 7;          // output column (W row)
        int k = x & 127;         // k index
        uint32_t addr = ((uint32_t)(j >> 6)) * 8192u
                      + ((uint32_t)(k >> 3)) * 512u
                      + ((uint32_t)((j >> 4) & 3)) * 128u
                      + ((uint32_t)(((j & 7) << 2) | (k & 3))) * 4u
                      + ((uint32_t)((j >> 3) & 1)) * 2u
                      + ((uint32_t)((k >> 2) & 1));
        g_Wtp[addr] = f2tf32(__ldg(W + x));
    }

    // bucket fill (int4-batched: 4 independent atomics in flight)
    const int E4 = E >> 2;
    const int4* dst4 = (const int4*)dst;
    for (int q = gt; q < E4; q += stride) {
        int4 d4 = __ldg(dst4 + q);
        int e = q * 4;
        int p0 = min(atomicAdd(&g_cnt[d4.x], 1), CAP - 1);
        int p1 = min(atomicAdd(&g_cnt[d4.y], 1), CAP - 1);
        int p2 = min(atomicAdd(&g_cnt[d4.z], 1), CAP - 1);
        int p3 = min(atomicAdd(&g_cnt[d4.w], 1), CAP - 1);
        g_eid[(size_t)d4.x * CAP + p0] = e;
        g_eid[(size_t)d4.y * CAP + p1] = e + 1;
        g_eid[(size_t)d4.z * CAP + p2] = e + 2;
        g_eid[(size_t)d4.w * CAP + p3] = e + 3;
    }
    for (int e = E4 * 4 + gt; e < E; e += stride) {
        int d = __ldg(dst + e);
        int pos = min(atomicAdd(&g_cnt[d], 1), CAP - 1);
        g_eid[(size_t)d * CAP + pos] = e;
    }
}

// ============================ gather ========================================
// One WARP owns one aligned 16-row fragment group (no cross-warp coupling):
//   accumulate 16 nodes into warp-private smem tile, __syncwarp, then emit
//   the fragment layout as 16 coalesced STG.128.
__global__ void __launch_bounds__(128)
gather_kernel(const float* __restrict__ h,
              const float* __restrict__ e_h,
              int N) {
    __shared__ float sm[4 * 16 * GLDP];

    const int wid  = threadIdx.x >> 5;
    const int lane = threadIdx.x & 31;
    const int base = (blockIdx.x * 4 + wid) * 16;   // node base of this warp
    if (base >= N) return;                          // N % 16 == 0: all-or-none

    float* wsm = sm + wid * 16 * GLDP;

    #pragma unroll 1
    for (int r = 0; r < 16; r++) {
        int n = base + r;
        int s = n * CAP;
        int t = s + min(__ldg(g_cnt + n), CAP);

        float4 a0 = make_float4(0.f, 0.f, 0.f, 0.f);
        float4 a1 = make_float4(0.f, 0.f, 0.f, 0.f);
        float4 a2 = make_float4(0.f, 0.f, 0.f, 0.f);
        float4 a3 = make_float4(0.f, 0.f, 0.f, 0.f);

        int i = s;
        for (; i + 7 < t; i += 8) {
            int e0 = __ldg(g_eid + i);
            int e1 = __ldg(g_eid + i + 1);
            int e2 = __ldg(g_eid + i + 2);
            int e3 = __ldg(g_eid + i + 3);
            int e4 = __ldg(g_eid + i + 4);
            int e5 = __ldg(g_eid + i + 5);
            int e6 = __ldg(g_eid + i + 6);
            int e7 = __ldg(g_eid + i + 7);
            float4 v0 = ((const float4*)(e_h + (size_t)e0 * D))[lane];
            float4 v1 = ((const float4*)(e_h + (size_t)e1 * D))[lane];
            float4 v2 = ((const float4*)(e_h + (size_t)e2 * D))[lane];
            float4 v3 = ((const float4*)(e_h + (size_t)e3 * D))[lane];
            float4 v4 = ((const float4*)(e_h + (size_t)e4 * D))[lane];
            float4 v5 = ((const float4*)(e_h + (size_t)e5 * D))[lane];
            float4 v6 = ((const float4*)(e_h + (size_t)e6 * D))[lane];
            float4 v7 = ((const float4*)(e_h + (size_t)e7 * D))[lane];
            a0.x += v0.x; a0.y += v0.y; a0.z += v0.z; a0.w += v0.w;
            a1.x += v1.x; a1.y += v1.y; a1.z += v1.z; a1.w += v1.w;
            a2.x += v2.x; a2.y += v2.y; a2.z += v2.z; a2.w += v2.w;
            a3.x += v3.x; a3.y += v3.y; a3.z += v3.z; a3.w += v3.w;
            a0.x += v4.x; a0.y += v4.y; a0.z += v4.z; a0.w += v4.w;
            a1.x += v5.x; a1.y += v5.y; a1.z += v5.z; a1.w += v5.w;
            a2.x += v6.x; a2.y += v6.y; a2.z += v6.z; a2.w += v6.w;
            a3.x += v7.x; a3.y += v7.y; a3.z += v7.z; a3.w += v7.w;
        }
        for (; i + 3 < t; i += 4) {
            int e0 = __ldg(g_eid + i);
            int e1 = __ldg(g_eid + i + 1);
            int e2 = __ldg(g_eid + i + 2);
            int e3 = __ldg(g_eid + i + 3);
            float4 v0 = ((const float4*)(e_h + (size_t)e0 * D))[lane];
            float4 v1 = ((const float4*)(e_h + (size_t)e1 * D))[lane];
            float4 v2 = ((const float4*)(e_h + (size_t)e2 * D))[lane];
            float4 v3 = ((const float4*)(e_h + (size_t)e3 * D))[lane];
            a0.x += v0.x; a0.y += v0.y; a0.z += v0.z; a0.w += v0.w;
            a1.x += v1.x; a1.y += v1.y; a1.z += v1.z; a1.w += v1.w;
            a2.x += v2.x; a2.y += v2.y; a2.z += v2.z; a2.w += v2.w;
            a3.x += v3.x; a3.y += v3.y; a3.z += v3.z; a3.w += v3.w;
        }
        for (; i < t; i++) {
            int e0 = __ldg(g_eid + i);
            float4 v0 = ((const float4*)(e_h + (size_t)e0 * D))[lane];
            a0.x += v0.x; a0.y += v0.y; a0.z += v0.z; a0.w += v0.w;
        }

        float4 hv = ((const float4*)(h + (size_t)n * D))[lane];
        float4 res;
        res.x = (a0.x + a1.x + a2.x + a3.x) * hv.x;
        res.y = (a0.y + a1.y + a2.y + a3.y) * hv.y;
        res.z = (a0.z + a1.z + a2.z + a3.z) * hv.z;
        res.w = (a0.w + a1.w + a2.w + a3.w) * hv.w;
        *(float4*)(wsm + r * GLDP + lane * 4) = res;
    }
    __syncwarp();

    // fragment-order emit: 16 coalesced STG.128 (one per ks), conflict-free LDS
    {
        const int tile = base >> 7;
        const int mg   = (base >> 5) & 3;
        const int mt   = (base >> 4) & 1;
        const int gid  = lane >> 2;
        const int j    = lane & 3;

        uint32_t* outp = g_aggp + (size_t)tile * 16384 + mg * 4096
                       + mt * 128 + lane * 4;
        #pragma unroll
        for (int ks = 0; ks < 16; ks++) {
            int kbase = ks * 8 + j;
            uint4 v;
            v.x = f2tf32(wsm[(size_t)gid * GLDP + kbase]);
            v.y = f2tf32(wsm[(size_t)(gid + 8) * GLDP + kbase]);
            v.z = f2tf32(wsm[(size_t)gid * GLDP + kbase + 4]);
            v.w = f2tf32(wsm[(size_t)(gid + 8) * GLDP + kbase + 4]);
            *(uint4*)(outp + ks * 256) = v;
        }
    }
}

// ====================== TF32 mma.sync GEMM (fragment-direct) ================
__device__ __forceinline__ void mma_tf32(float* c, const uint32_t* a, const uint32_t* bb) {
    asm volatile(
        "mma.sync.aligned.m16n8k8.row.col.f32.tf32.tf32.f32 "
        "{%0,%1,%2,%3}, {%4,%5,%6,%7}, {%8,%9}, {%0,%1,%2,%3};"
        : "+f"(c[0]), "+f"(c[1]), "+f"(c[2]), "+f"(c[3])
        : "r"(a[0]), "r"(a[1]), "r"(a[2]), "r"(a[3]), "r"(bb[0]), "r"(bb[1]));
}

__global__ void __launch_bounds__(256, 2)
gemm_mma_kernel(const float* __restrict__ b,
                const float* __restrict__ norm,
                float* __restrict__ out,
                int N) {
    const int tid  = threadIdx.x;
    const int wid  = tid >> 5;
    const int lane = tid & 31;
    const int mg   = wid & 3;
    const int ng   = wid >> 2;
    const int rowBase = blockIdx.x * 128;

    const uint32_t* Ab = g_aggp + (size_t)blockIdx.x * 16384 + mg * 4096 + lane * 4;
    const uint32_t* Bb = g_Wtp + ng * 8192 + lane * 4;

    float acc[16][4];
    #pragma unroll
    for (int q = 0; q < 16; q++)
        #pragma unroll
        for (int j = 0; j < 4; j++) acc[q][j] = 0.0f;

    #pragma unroll
    for (int ks = 0; ks < 16; ks++) {
        uint32_t a[2][4];
        #pragma unroll
        for (int mt = 0; mt < 2; mt++) {
            uint4 av = __ldg((const uint4*)(Ab + ks * 256 + mt * 128));
            a[mt][0] = av.x; a[mt][1] = av.y; a[mt][2] = av.z; a[mt][3] = av.w;
        }
        uint32_t bf[8][2];
        #pragma unroll
        for (int nt2 = 0; nt2 < 4; nt2++) {
            uint4 bv = __ldg((const uint4*)(Bb + ks * 512 + nt2 * 128));
            bf[nt2 * 2 + 0][0] = bv.x; bf[nt2 * 2 + 0][1] = bv.y;
            bf[nt2 * 2 + 1][0] = bv.z; bf[nt2 * 2 + 1][1] = bv.w;
        }
        #pragma unroll
        for (int mt = 0; mt < 2; mt++)
            #pragma unroll
            for (int nt = 0; nt < 8; nt++)
                mma_tf32(acc[mt * 8 + nt], a[mt], bf[nt]);
    }

    const int gID = lane >> 2;
    const int tig = lane & 3;
    const int mBase = mg * 32;
    const int nBase = ng * 64;

    #pragma unroll
    for (int mt = 0; mt < 2; mt++) {
        #pragma unroll
        for (int half = 0; half < 2; half++) {
            int m = rowBase + mBase + mt * 16 + half * 8 + gID;
            if (m >= N) continue;
            float nm = __ldg(norm + m);
            #pragma unroll
            for (int nt = 0; nt < 8; nt++) {
                int jcol = nBase + (nt >> 1) * 16 + (nt & 1) * 8;
                float2 bb = *(const float2*)(b + jcol + tig * 2);
                float2 r;
                r.x = (acc[mt * 8 + nt][half * 2 + 0] + bb.x) * nm;
                r.y = (acc[mt * 8 + nt][half * 2 + 1] + bb.y) * nm;
                *(float2*)(out + (size_t)m * D + jcol + tig * 2) = r;
            }
        }
    }
}

// ============================ launch ========================================
extern "C" void kernel_launch(void* const* d_in, const int* in_sizes, int n_in,
                              void* d_out, int out_size) {
    const float* h    = (const float*)d_in[0];
    const float* e_h  = (const float*)d_in[1];
    const float* norm = (const float*)d_in[2];
    const int*   dst  = (const int*)d_in[3];
    const float* W    = (const float*)d_in[4];
    const float* b    = (const float*)d_in[5];
    float*       out  = (float*)d_out;

    const int N = in_sizes[2];
    const int E = in_sizes[3];

    int* cntp = nullptr;
    cudaGetSymbolAddress((void**)&cntp, g_cnt);
    cudaMemsetAsync(cntp, 0, (size_t)N * sizeof(int), 0);

    {   // one int4 per thread
        int blocks = ((E >> 2) + 255) / 256;
        fill_kernel<<<blocks, 256>>>(dst, W, E);
    }
    {   // one warp per 16-node group
        int groups = (N + 15) / 16;              // 3125
        int blocks = (groups + 3) / 4;           // 4 warps/block
        gather_kernel<<<blocks, 128>>>(h, e_h, N);
    }
    gemm_mma_kernel<<<(N + 127) / 128, 256>>>(b, norm, out, N);
}